// round 9
// baseline (speedup 1.0000x reference)
#include <cuda_runtime.h>
#include <cuda_fp16.h>
#include <cstdint>

#define D 128
#define N_TGT 40000
#define N_EDGE 640000
#define NTILES (N_EDGE / 128)
#define SROW 68                 // u32 per fp16 smem row (64 data + 4 pad) = 272 B
#define XBUF (128 * SROW)       // 8704 u32 per X buffer

// ---------------- scratch ----------------
__device__ float g_sums[(size_t)N_TGT * D];
__device__ float g_counts[N_TGT];

__global__ void zero_scratch_kernel() {
    const int n = N_TGT * D;
    const int total = n + N_TGT;
    for (int i = blockIdx.x * blockDim.x + threadIdx.x; i < total;
         i += gridDim.x * blockDim.x) {
        if (i < n) g_sums[i] = 0.f;
        else       g_counts[i - n] = 0.f;
    }
}

// ---------------- helpers ----------------
__device__ __forceinline__ uint32_t smem_addr_u32(const void* p) {
    uint32_t a;
    asm("{ .reg .u64 t; cvta.to.shared.u64 t, %1; cvt.u32.u64 %0, t; }"
        : "=r"(a) : "l"(p));
    return a;
}
__device__ __forceinline__ uint32_t ph2(float x, float y) {
    __half2 h = __floats2half2_rn(x, y);
    return *(uint32_t*)&h;
}
__device__ __forceinline__ void ldsm_x4(uint32_t& r0, uint32_t& r1,
                                        uint32_t& r2, uint32_t& r3, uint32_t a) {
    asm volatile("ldmatrix.sync.aligned.m8n8.x4.shared.b16 {%0,%1,%2,%3}, [%4];"
        : "=r"(r0), "=r"(r1), "=r"(r2), "=r"(r3) : "r"(a));
}
__device__ __forceinline__ void ldsm_x2(uint32_t& r0, uint32_t& r1, uint32_t a) {
    asm volatile("ldmatrix.sync.aligned.m8n8.x2.shared.b16 {%0,%1}, [%2];"
        : "=r"(r0), "=r"(r1) : "r"(a));
}
__device__ __forceinline__ void mma16(float* d, uint32_t a0, uint32_t a1,
                                      uint32_t a2, uint32_t a3,
                                      uint32_t b0, uint32_t b1) {
    asm volatile(
        "mma.sync.aligned.m16n8k16.row.col.f32.f16.f16.f32 "
        "{%0,%1,%2,%3},{%4,%5,%6,%7},{%8,%9},{%0,%1,%2,%3};"
        : "+f"(d[0]), "+f"(d[1]), "+f"(d[2]), "+f"(d[3])
        : "r"(a0), "r"(a1), "r"(a2), "r"(a3), "r"(b0), "r"(b1));
}
__device__ __forceinline__ void red_v4(float* p, float a, float b,
                                       float c, float d) {
    asm volatile("red.relaxed.gpu.global.add.v4.f32 [%0], {%1, %2, %3, %4};"
        :: "l"(p), "f"(a), "f"(b), "f"(c), "f"(d) : "memory");
}
#define BAR_CONSUMERS() asm volatile("bar.sync 1, 256;" ::: "memory")

// ---------------- smem layout (u32 offsets) ----------------
#define UOFF_W1  0
#define UOFF_W2  8704
#define UOFF_XA  17408          // 2 buffers: 17408, 26112
#define UOFF_XB  34816          // 2 buffers: 34816, 43520
#define UOFF_SUM 52224          // float[256]
#define UOFF_SQ  52480          // float[256]
#define UOFF_TI  52736          // int[2][128]
#define UOFF_G   52992
#define UOFF_B   53120
#define SMEM_U32 53248
#define SMEM_BYTES (SMEM_U32 * 4)   // 212992

// ---- producer: stage one edge-row of tile into buffer `buf` ----
__device__ __forceinline__ void stage_tile(
    int tile, int buf, int prow,
    const float* __restrict__ src_feat, const float* __restrict__ tgt_feat,
    const float* __restrict__ edge_feat,
    const int* __restrict__ src_idx, const int* __restrict__ tgt_idx,
    uint32_t* __restrict__ smu)
{
    if (tile >= NTILES) return;
    const int m1 = tile * 128;
    const int si = src_idx[m1 + prow];
    const int ti = tgt_idx[m1 + prow];
    ((int*)(smu + UOFF_TI))[buf * 128 + prow] = ti;
    const float* __restrict__ sr = src_feat + (size_t)si * D;
    const float* __restrict__ tr = tgt_feat + (size_t)ti * D;
    const float* __restrict__ er = edge_feat + (size_t)(m1 + prow) * D;
    uint32_t* __restrict__ xa = smu + UOFF_XA + buf * XBUF + prow * SROW;
    uint32_t* __restrict__ xb = smu + UOFF_XB + buf * XBUF + prow * SROW;
#pragma unroll
    for (int c = 0; c < 8; c++) {
        float4 a[4], b[4], e[4];
#pragma unroll
        for (int q = 0; q < 4; q++) {
            a[q] = *(const float4*)(sr + c * 16 + q * 4);
            b[q] = *(const float4*)(tr + c * 16 + q * 4);
            e[q] = *(const float4*)(er + c * 16 + q * 4);
        }
#pragma unroll
        for (int q = 0; q < 4; q++) {
            uint2 ua, ue;
            ua.x = ph2(a[q].x + b[q].x, a[q].y + b[q].y);
            ua.y = ph2(a[q].z + b[q].z, a[q].w + b[q].w);
            ue.x = ph2(e[q].x, e[q].y);
            ue.y = ph2(e[q].z, e[q].w);
            *(uint2*)(xa + c * 8 + q * 2) = ua;
            *(uint2*)(xb + c * 8 + q * 2) = ue;
        }
    }
}

// ======================= EDGE kernel (warp-specialized) ====================
__global__ void __launch_bounds__(384, 1)
edge_kernel(const float* __restrict__ src_feat,
            const float* __restrict__ tgt_feat,
            const float* __restrict__ edge_feat,
            const float* __restrict__ W1,
            const float* __restrict__ W2,
            const float* __restrict__ gamma,
            const float* __restrict__ beta,
            const int*   __restrict__ src_idx,
            const int*   __restrict__ tgt_idx,
            float*       __restrict__ out)
{
    extern __shared__ uint32_t smu[];
    const uint32_t smb = smem_addr_u32(smu);

    float* s_sum = (float*)(smu + UOFF_SUM);
    float* s_sq  = (float*)(smu + UOFF_SQ);
    int*   s_ti  = (int*)(smu + UOFF_TI);
    float* s_g   = (float*)(smu + UOFF_G);
    float* s_b   = (float*)(smu + UOFF_B);

    const int tid  = threadIdx.x;
    const int wid  = tid >> 5;
    const int lane = tid & 31;
    const int g    = lane >> 2;
    const int t4   = lane & 3;
    const int wr   = wid & 3;     // consumer: row band
    const int wc   = wid >> 2;    // consumer: column half (0/1 for wid<8)

    // ldmatrix lane geometry
    const int a_r  = (lane & 7) + ((lane >> 3) & 1) * 8;
    const int a_cu = ((lane >> 4) & 1) * 4;
    const int lb   = lane & 15;
    const int b_r  = lb & 7;
    const int b_cu = ((lb >> 3) & 1) * 4;

    if (tid < 128) { s_g[tid] = gamma[tid]; s_b[tid] = beta[tid]; }

    // stage both weight tiles once (fp16), all threads
    for (int i = tid; i < 128 * 32; i += 384) {
        int n = i >> 5, k4 = (i & 31) << 2;
        float4 a = *(const float4*)(W1 + n * D + k4);
        float4 b = *(const float4*)(W2 + n * D + k4);
        uint2 ua, ub;
        ua.x = ph2(a.x, a.y); ua.y = ph2(a.z, a.w);
        ub.x = ph2(b.x, b.y); ub.y = ph2(b.z, b.w);
        *(uint2*)(smu + UOFF_W1 + n * SROW + (k4 >> 1)) = ua;
        *(uint2*)(smu + UOFF_W2 + n * SROW + (k4 >> 1)) = ub;
    }

    // prologue: producers stage the first tile into buffer 0
    if (tid >= 256)
        stage_tile(blockIdx.x, 0, tid - 256,
                   src_feat, tgt_feat, edge_feat, src_idx, tgt_idx, smu);
    __syncthreads();

    int p = 0;
    for (int tile = blockIdx.x; tile < NTILES; tile += gridDim.x) {
        if (tid < 256) {
            // =================== CONSUMER ===================
            const int m0 = tile * 128;
            const uint32_t xa_off = UOFF_XA + p * XBUF;
            const uint32_t xb_off = UOFF_XB + p * XBUF;

            float acc[2][8][4];
#pragma unroll
            for (int mt = 0; mt < 2; mt++)
#pragma unroll
                for (int nt = 0; nt < 8; nt++)
#pragma unroll
                    for (int j = 0; j < 4; j++) acc[mt][nt][j] = 0.f;

            // pass 1: acc += XA @ W1^T
#pragma unroll
            for (int ks = 0; ks < 8; ks++) {
                uint32_t a0[2], a1[2], a2[2], a3[2];
#pragma unroll
                for (int mt = 0; mt < 2; mt++) {
                    uint32_t ad = smb + (xa_off + (wr * 32 + mt * 16 + a_r) * SROW
                                         + ks * 8 + a_cu) * 4;
                    ldsm_x4(a0[mt], a1[mt], a2[mt], a3[mt], ad);
                }
#pragma unroll
                for (int nt = 0; nt < 8; nt++) {
                    uint32_t bd = smb + (UOFF_W1 + (wc * 64 + nt * 8 + b_r) * SROW
                                         + ks * 8 + b_cu) * 4;
                    uint32_t b0, b1;
                    ldsm_x2(b0, b1, bd);
                    mma16(acc[0][nt], a0[0], a1[0], a2[0], a3[0], b0, b1);
                    mma16(acc[1][nt], a0[1], a1[1], a2[1], a3[1], b0, b1);
                }
            }
            // pass 2: acc += XB @ W2^T (disjoint buffers, no sync)
#pragma unroll
            for (int ks = 0; ks < 8; ks++) {
                uint32_t a0[2], a1[2], a2[2], a3[2];
#pragma unroll
                for (int mt = 0; mt < 2; mt++) {
                    uint32_t ad = smb + (xb_off + (wr * 32 + mt * 16 + a_r) * SROW
                                         + ks * 8 + a_cu) * 4;
                    ldsm_x4(a0[mt], a1[mt], a2[mt], a3[mt], ad);
                }
#pragma unroll
                for (int nt = 0; nt < 8; nt++) {
                    uint32_t bd = smb + (UOFF_W2 + (wc * 64 + nt * 8 + b_r) * SROW
                                         + ks * 8 + b_cu) * 4;
                    uint32_t b0, b1;
                    ldsm_x2(b0, b1, bd);
                    mma16(acc[0][nt], a0[0], a1[0], a2[0], a3[0], b0, b1);
                    mma16(acc[1][nt], a0[1], a1[1], a2[1], a3[1], b0, b1);
                }
            }

            // silu + LN partials
#pragma unroll
            for (int mt = 0; mt < 2; mt++) {
#pragma unroll
                for (int h = 0; h < 2; h++) {
                    float s = 0.f, q = 0.f;
#pragma unroll
                    for (int nt = 0; nt < 8; nt++) {
#pragma unroll
                        for (int j = 0; j < 2; j++) {
                            float v  = acc[mt][nt][h * 2 + j];
                            float sv = v / (1.f + __expf(-v));
                            acc[mt][nt][h * 2 + j] = sv;
                            s += sv; q += sv * sv;
                        }
                    }
                    s += __shfl_xor_sync(0xffffffffu, s, 1);
                    s += __shfl_xor_sync(0xffffffffu, s, 2);
                    q += __shfl_xor_sync(0xffffffffu, q, 1);
                    q += __shfl_xor_sync(0xffffffffu, q, 2);
                    if (t4 == 0) {
                        int row = wr * 32 + mt * 16 + h * 8 + g;
                        s_sum[wc * 128 + row] = s;
                        s_sq[wc * 128 + row]  = q;
                    }
                }
            }
            BAR_CONSUMERS();

            // LN + residual + out + scatter
#pragma unroll
            for (int mt = 0; mt < 2; mt++) {
#pragma unroll
                for (int h = 0; h < 2; h++) {
                    const int row = wr * 32 + mt * 16 + h * 8 + g;
                    const float tsum = s_sum[row] + s_sum[128 + row];
                    const float tsq  = s_sq[row]  + s_sq[128 + row];
                    const float mean = tsum * (1.f / 128.f);
                    const float inv  = rsqrtf(tsq * (1.f / 128.f) - mean * mean + 1e-5f);
                    const int    t   = s_ti[p * 128 + row];
                    const size_t gm  = (size_t)(m0 + row);
                    float* __restrict__ srow = g_sums + (size_t)t * D;
                    const float* __restrict__ er = edge_feat + gm * D;
                    float* __restrict__ orow = out + gm * D;
#pragma unroll
                    for (int nt = 0; nt < 8; nt++) {
                        const int c = wc * 64 + nt * 8 + t4 * 2;
                        float a0 = (acc[mt][nt][h * 2 + 0] - mean) * inv * s_g[c + 0] + s_b[c + 0];
                        float a1 = (acc[mt][nt][h * 2 + 1] - mean) * inv * s_g[c + 1] + s_b[c + 1];
                        float p0 = __shfl_xor_sync(0xffffffffu, a0, 1);
                        float p1 = __shfl_xor_sync(0xffffffffu, a1, 1);
                        if ((t4 & 1) == 0) {
                            float4 rs = *(const float4*)(er + c);
                            float4 o;
                            o.x = rs.x + a0; o.y = rs.y + a1;
                            o.z = rs.z + p0; o.w = rs.w + p1;
                            *(float4*)(orow + c) = o;
                            red_v4(srow + c, a0, a1, p0, p1);
                        }
                    }
                    if (wc == 0 && t4 == 0) atomicAdd(g_counts + t, 1.f);
                }
            }
        } else {
            // =================== PRODUCER ===================
            stage_tile(tile + gridDim.x, p ^ 1, tid - 256,
                       src_feat, tgt_feat, edge_feat, src_idx, tgt_idx, smu);
        }
        __syncthreads();
        p ^= 1;
    }
}

// ======================= NODE kernel (SIMT, small) =======================
#define TILE_M  128
#define KC      32
#define SST     132

__global__ void __launch_bounds__(256)
node_kernel(const float* __restrict__ tgt_feat,
            const float* __restrict__ W1,       // We2t
            const float* __restrict__ W2,       // Wt2t
            const float* __restrict__ gamma,
            const float* __restrict__ beta,
            float*       __restrict__ out,
            int M)
{
    __shared__ float xs[KC][SST];
    __shared__ float ws[KC][SST];
    __shared__ float s_inv[TILE_M];

    const int tid = threadIdx.x;
    const int tx  = tid & 15;
    const int ty  = tid >> 4;
    const int m0  = blockIdx.x * TILE_M;

    for (int i = tid; i < TILE_M; i += 256) {
        int row = m0 + i;
        s_inv[i] = (row < M) ? 1.f / fmaxf(g_counts[row], 1.f) : 0.f;
    }
    __syncthreads();

    float acc[8][8];
#pragma unroll
    for (int r = 0; r < 8; r++)
#pragma unroll
        for (int c = 0; c < 8; c++) acc[r][c] = 0.f;

#pragma unroll 1
    for (int pass = 0; pass < 2; pass++) {
        const float* __restrict__ W = pass ? W2 : W1;
#pragma unroll 1
        for (int kc = 0; kc < D / KC; kc++) {
            const int k0 = kc * KC;
            for (int i = tid; i < D * KC; i += 256) {
                int n = i >> 5, kl = i & 31;
                ws[kl][n] = W[n * D + k0 + kl];
            }
            for (int i = tid; i < TILE_M * KC; i += 256) {
                int m = i >> 5, kl = i & 31;
                float v = 0.f;
                long gm = (long)(m0 + m);
                if (gm < M) {
                    if (pass == 0) v = g_sums[gm * D + k0 + kl] * s_inv[m];
                    else           v = tgt_feat[gm * D + k0 + kl];
                }
                xs[kl][m] = v;
            }
            __syncthreads();
#pragma unroll
            for (int k = 0; k < KC; k++) {
                float4 xa = *(const float4*)&xs[k][ty * 4];
                float4 xb = *(const float4*)&xs[k][64 + ty * 4];
                float4 wa = *(const float4*)&ws[k][tx * 4];
                float4 wb = *(const float4*)&ws[k][64 + tx * 4];
                float xv[8] = {xa.x, xa.y, xa.z, xa.w, xb.x, xb.y, xb.z, xb.w};
                float wv[8] = {wa.x, wa.y, wa.z, wa.w, wb.x, wb.y, wb.z, wb.w};
#pragma unroll
                for (int r = 0; r < 8; r++)
#pragma unroll
                    for (int c = 0; c < 8; c++) acc[r][c] += xv[r] * wv[c];
            }
            __syncthreads();
        }
    }

    float g[8], b[8];
#pragma unroll
    for (int c = 0; c < 8; c++) {
        int n = (c < 4) ? (tx * 4 + c) : (64 + tx * 4 + (c - 4));
        g[c] = gamma[n];
        b[c] = beta[n];
    }

#pragma unroll
    for (int r = 0; r < 8; r++) {
        const int mrow = (r < 4) ? (ty * 4 + r) : (64 + ty * 4 + (r - 4));
        const long gm  = (long)(m0 + mrow);

        float sum = 0.f, sq = 0.f;
#pragma unroll
        for (int c = 0; c < 8; c++) {
            float v  = acc[r][c];
            float sv = v / (1.f + __expf(-v));
            acc[r][c] = sv;
            sum += sv; sq += sv * sv;
        }
#pragma unroll
        for (int o = 8; o >= 1; o >>= 1) {
            sum += __shfl_xor_sync(0xffffffffu, sum, o);
            sq  += __shfl_xor_sync(0xffffffffu, sq,  o);
        }
        const float mean = sum * (1.f / 128.f);
        const float var  = sq * (1.f / 128.f) - mean * mean;
        const float inv  = rsqrtf(var + 1e-5f);

        if (gm >= M) continue;

        const float* __restrict__ resrow = tgt_feat + gm * D;
        float4 r0 = *(const float4*)&resrow[tx * 4];
        float4 r1 = *(const float4*)&resrow[64 + tx * 4];
        float a0 = (acc[r][0] - mean) * inv * g[0] + b[0];
        float a1 = (acc[r][1] - mean) * inv * g[1] + b[1];
        float a2 = (acc[r][2] - mean) * inv * g[2] + b[2];
        float a3 = (acc[r][3] - mean) * inv * g[3] + b[3];
        float a4 = (acc[r][4] - mean) * inv * g[4] + b[4];
        float a5 = (acc[r][5] - mean) * inv * g[5] + b[5];
        float a6 = (acc[r][6] - mean) * inv * g[6] + b[6];
        float a7 = (acc[r][7] - mean) * inv * g[7] + b[7];
        *(float4*)&out[gm * D + tx * 4] =
            make_float4(r0.x + a0, r0.y + a1, r0.z + a2, r0.w + a3);
        *(float4*)&out[gm * D + 64 + tx * 4] =
            make_float4(r1.x + a4, r1.y + a5, r1.z + a6, r1.w + a7);
    }
}

// ======================= launch =======================
extern "C" void kernel_launch(void* const* d_in, const int* in_sizes, int n_in,
                              void* d_out, int out_size) {
    const float* src_feat  = (const float*)d_in[0];
    const float* tgt_feat  = (const float*)d_in[1];
    const float* edge_feat = (const float*)d_in[2];
    const float* Ws2e      = (const float*)d_in[3];
    const float* We2e      = (const float*)d_in[4];
    const float* We2t      = (const float*)d_in[5];
    const float* Wt2t      = (const float*)d_in[6];
    const float* gamma1    = (const float*)d_in[7];
    const float* beta1     = (const float*)d_in[8];
    const float* gamma2    = (const float*)d_in[9];
    const float* beta2     = (const float*)d_in[10];
    const int*   src_idx   = (const int*)d_in[11];
    const int*   tgt_idx   = (const int*)d_in[12];
    float*       out       = (float*)d_out;

    cudaFuncSetAttribute(edge_kernel,
                         cudaFuncAttributeMaxDynamicSharedMemorySize, SMEM_BYTES);

    zero_scratch_kernel<<<2048, 256>>>();

    edge_kernel<<<148, 384, SMEM_BYTES>>>(
        src_feat, tgt_feat, edge_feat, Ws2e, We2e, gamma1, beta1,
        src_idx, tgt_idx, out);

    node_kernel<<<(N_TGT + TILE_M - 1) / TILE_M, 256>>>(
        tgt_feat, We2t, Wt2t, gamma2, beta2, out + (size_t)N_EDGE * D, N_TGT);
}

// round 10
// speedup vs baseline: 1.6527x; 1.6527x over previous
#include <cuda_runtime.h>
#include <cuda_fp16.h>
#include <cstdint>

#define D 128
#define N_TGT 40000
#define N_EDGE 640000
#define NTILES (N_EDGE / 128)
#define SROW 68                 // u32 per fp16 smem row (64 data + 4 pad)
#define XBLK (128 * SROW)       // 8704 u32 per X buffer

// ---------------- scratch ----------------
__device__ float g_sums[(size_t)N_TGT * D];
__device__ float g_counts[N_TGT];

__global__ void zero_scratch_kernel() {
    const int n = N_TGT * D;
    const int total = n + N_TGT;
    for (int i = blockIdx.x * blockDim.x + threadIdx.x; i < total;
         i += gridDim.x * blockDim.x) {
        if (i < n) g_sums[i] = 0.f;
        else       g_counts[i - n] = 0.f;
    }
}

// ---------------- helpers ----------------
__device__ __forceinline__ uint32_t smem_addr_u32(const void* p) {
    uint32_t a;
    asm("{ .reg .u64 t; cvta.to.shared.u64 t, %1; cvt.u32.u64 %0, t; }"
        : "=r"(a) : "l"(p));
    return a;
}
__device__ __forceinline__ uint32_t ph2(float x, float y) {
    __half2 h = __floats2half2_rn(x, y);
    return *(uint32_t*)&h;
}
__device__ __forceinline__ void ldsm_x4(uint32_t& r0, uint32_t& r1,
                                        uint32_t& r2, uint32_t& r3, uint32_t a) {
    asm volatile("ldmatrix.sync.aligned.m8n8.x4.shared.b16 {%0,%1,%2,%3}, [%4];"
        : "=r"(r0), "=r"(r1), "=r"(r2), "=r"(r3) : "r"(a));
}
__device__ __forceinline__ void ldsm_x2(uint32_t& r0, uint32_t& r1, uint32_t a) {
    asm volatile("ldmatrix.sync.aligned.m8n8.x2.shared.b16 {%0,%1}, [%2];"
        : "=r"(r0), "=r"(r1) : "r"(a));
}
__device__ __forceinline__ void mma16(float* d, uint32_t a0, uint32_t a1,
                                      uint32_t a2, uint32_t a3,
                                      uint32_t b0, uint32_t b1) {
    asm volatile(
        "mma.sync.aligned.m16n8k16.row.col.f32.f16.f16.f32 "
        "{%0,%1,%2,%3},{%4,%5,%6,%7},{%8,%9},{%0,%1,%2,%3};"
        : "+f"(d[0]), "+f"(d[1]), "+f"(d[2]), "+f"(d[3])
        : "r"(a0), "r"(a1), "r"(a2), "r"(a3), "r"(b0), "r"(b1));
}
__device__ __forceinline__ void red_v4(float* p, float a, float b,
                                       float c, float d) {
    asm volatile("red.relaxed.gpu.global.add.v4.f32 [%0], {%1, %2, %3, %4};"
        :: "l"(p), "f"(a), "f"(b), "f"(c), "f"(d) : "memory");
}
__device__ __forceinline__ void barg(int gid) {
    asm volatile("bar.sync %0, 256;" :: "r"(gid + 1) : "memory");
}

// ---------------- smem layout (u32 offsets) ----------------
#define UOFF_W1  0
#define UOFF_W2  8704
#define UOFF_X   17408          // group g: XA = UOFF_X + g*2*XBLK, XB = XA + XBLK
#define UOFF_SUM 52224          // + g*256 floats
#define UOFF_SQ  52736          // + g*256 floats
#define UOFF_G   53248
#define UOFF_B   53376
#define SMEM_U32 53504
#define SMEM_BYTES (SMEM_U32 * 4)   // 214016

// ======================= EDGE kernel (2 groups x 256 threads) ==============
__global__ void __launch_bounds__(512, 1)
edge_kernel(const float* __restrict__ src_feat,
            const float* __restrict__ tgt_feat,
            const float* __restrict__ edge_feat,
            const float* __restrict__ W1,
            const float* __restrict__ W2,
            const float* __restrict__ gamma,
            const float* __restrict__ beta,
            const int*   __restrict__ src_idx,
            const int*   __restrict__ tgt_idx,
            float*       __restrict__ out)
{
    extern __shared__ uint32_t smu[];
    const uint32_t smb = smem_addr_u32(smu);

    const int tid  = threadIdx.x;
    const int gid  = tid >> 8;          // group 0 / 1
    const int lt   = tid & 255;         // local tid within group
    const int wid  = lt >> 5;           // local warp 0-7
    const int lane = tid & 31;
    const int g    = lane >> 2;
    const int t4   = lane & 3;
    const int wr   = wid & 3;           // row band
    const int wc   = wid >> 3;          // WRONG? no: see below
    // consumer geometry: 8 warps = 4 row-bands x 2 col-halves
    const int wcol = wid >> 2;          // column half 0/1

    float* s_sum = (float*)(smu + UOFF_SUM + gid * 256);
    float* s_sq  = (float*)(smu + UOFF_SQ  + gid * 256);
    float* s_g   = (float*)(smu + UOFF_G);
    float* s_b   = (float*)(smu + UOFF_B);
    const uint32_t xa_off = UOFF_X + gid * 2 * XBLK;
    const uint32_t xb_off = xa_off + XBLK;

    // ldmatrix lane geometry
    const int a_r  = (lane & 7) + ((lane >> 3) & 1) * 8;
    const int a_cu = ((lane >> 4) & 1) * 4;
    const int lb   = lane & 15;
    const int b_r  = lb & 7;
    const int b_cu = ((lb >> 3) & 1) * 4;

    if (tid < 128) { s_g[tid] = gamma[tid]; s_b[tid] = beta[tid]; }

    // stage both weight tiles once (fp16), all 512 threads
    for (int i = tid; i < 128 * 32; i += 512) {
        int n = i >> 5, k4 = (i & 31) << 2;
        float4 a = *(const float4*)(W1 + n * D + k4);
        float4 b = *(const float4*)(W2 + n * D + k4);
        uint2 ua, ub;
        ua.x = ph2(a.x, a.y); ua.y = ph2(a.z, a.w);
        ub.x = ph2(b.x, b.y); ub.y = ph2(b.z, b.w);
        *(uint2*)(smu + UOFF_W1 + n * SROW + (k4 >> 1)) = ua;
        *(uint2*)(smu + UOFF_W2 + n * SROW + (k4 >> 1)) = ub;
    }
    __syncthreads();

    for (int tile = blockIdx.x * 2 + gid; tile < NTILES; tile += gridDim.x * 2) {
        const int m0 = tile * 128;

        // ---- stage X0 = src[si]+tgt[ti], X1 = edge (fp16) ----
#pragma unroll
        for (int j = 0; j < 16; j++) {
            int i = lt + 256 * j;
            int row = i >> 5, k4 = (i & 31) << 2;
            int si = src_idx[m0 + row];
            int ti = tgt_idx[m0 + row];
            float4 a = *(const float4*)(src_feat + (size_t)si * D + k4);
            float4 b = *(const float4*)(tgt_feat + (size_t)ti * D + k4);
            float4 e = *(const float4*)(edge_feat + (size_t)(m0 + row) * D + k4);
            uint2 u0, u1;
            u0.x = ph2(a.x + b.x, a.y + b.y);
            u0.y = ph2(a.z + b.z, a.w + b.w);
            u1.x = ph2(e.x, e.y);
            u1.y = ph2(e.z, e.w);
            *(uint2*)(smu + xa_off + row * SROW + (k4 >> 1)) = u0;
            *(uint2*)(smu + xb_off + row * SROW + (k4 >> 1)) = u1;
        }
        barg(gid);

        float acc[2][8][4];
#pragma unroll
        for (int mt = 0; mt < 2; mt++)
#pragma unroll
            for (int nt = 0; nt < 8; nt++)
#pragma unroll
                for (int j = 0; j < 4; j++) acc[mt][nt][j] = 0.f;

        // ---- pass 1: acc += XA @ W1^T ----
#pragma unroll
        for (int ks = 0; ks < 8; ks++) {
            uint32_t a0[2], a1[2], a2[2], a3[2];
#pragma unroll
            for (int mt = 0; mt < 2; mt++) {
                uint32_t ad = smb + (xa_off + (wr * 32 + mt * 16 + a_r) * SROW
                                     + ks * 8 + a_cu) * 4;
                ldsm_x4(a0[mt], a1[mt], a2[mt], a3[mt], ad);
            }
#pragma unroll
            for (int nt = 0; nt < 8; nt++) {
                uint32_t bd = smb + (UOFF_W1 + (wcol * 64 + nt * 8 + b_r) * SROW
                                     + ks * 8 + b_cu) * 4;
                uint32_t b0, b1;
                ldsm_x2(b0, b1, bd);
                mma16(acc[0][nt], a0[0], a1[0], a2[0], a3[0], b0, b1);
                mma16(acc[1][nt], a0[1], a1[1], a2[1], a3[1], b0, b1);
            }
        }
        // ---- pass 2: acc += XB @ W2^T (disjoint buffers, no sync) ----
#pragma unroll
        for (int ks = 0; ks < 8; ks++) {
            uint32_t a0[2], a1[2], a2[2], a3[2];
#pragma unroll
            for (int mt = 0; mt < 2; mt++) {
                uint32_t ad = smb + (xb_off + (wr * 32 + mt * 16 + a_r) * SROW
                                     + ks * 8 + a_cu) * 4;
                ldsm_x4(a0[mt], a1[mt], a2[mt], a3[mt], ad);
            }
#pragma unroll
            for (int nt = 0; nt < 8; nt++) {
                uint32_t bd = smb + (UOFF_W2 + (wcol * 64 + nt * 8 + b_r) * SROW
                                     + ks * 8 + b_cu) * 4;
                uint32_t b0, b1;
                ldsm_x2(b0, b1, bd);
                mma16(acc[0][nt], a0[0], a1[0], a2[0], a3[0], b0, b1);
                mma16(acc[1][nt], a0[1], a1[1], a2[1], a3[1], b0, b1);
            }
        }

        // ---- silu + LN partials ----
#pragma unroll
        for (int mt = 0; mt < 2; mt++) {
#pragma unroll
            for (int h = 0; h < 2; h++) {
                float s = 0.f, q = 0.f;
#pragma unroll
                for (int nt = 0; nt < 8; nt++) {
#pragma unroll
                    for (int j = 0; j < 2; j++) {
                        float v  = acc[mt][nt][h * 2 + j];
                        float sv = v / (1.f + __expf(-v));
                        acc[mt][nt][h * 2 + j] = sv;
                        s += sv; q += sv * sv;
                    }
                }
                s += __shfl_xor_sync(0xffffffffu, s, 1);
                s += __shfl_xor_sync(0xffffffffu, s, 2);
                q += __shfl_xor_sync(0xffffffffu, q, 1);
                q += __shfl_xor_sync(0xffffffffu, q, 2);
                if (t4 == 0) {
                    int row = wr * 32 + mt * 16 + h * 8 + g;
                    s_sum[wcol * 128 + row] = s;
                    s_sq[wcol * 128 + row]  = q;
                }
            }
        }
        barg(gid);

        // ---- LN + residual + out + scatter ----
#pragma unroll
        for (int mt = 0; mt < 2; mt++) {
#pragma unroll
            for (int h = 0; h < 2; h++) {
                const int row = wr * 32 + mt * 16 + h * 8 + g;
                const float tsum = s_sum[row] + s_sum[128 + row];
                const float tsq  = s_sq[row]  + s_sq[128 + row];
                const float mean = tsum * (1.f / 128.f);
                const float inv  = rsqrtf(tsq * (1.f / 128.f) - mean * mean + 1e-5f);
                const int    t   = tgt_idx[m0 + row];
                const size_t gm  = (size_t)(m0 + row);
                float* __restrict__ srow = g_sums + (size_t)t * D;
                const float* __restrict__ er = edge_feat + gm * D;
                float* __restrict__ orow = out + gm * D;
#pragma unroll
                for (int nt = 0; nt < 8; nt++) {
                    const int c = wcol * 64 + nt * 8 + t4 * 2;
                    float a0 = (acc[mt][nt][h * 2 + 0] - mean) * inv * s_g[c + 0] + s_b[c + 0];
                    float a1 = (acc[mt][nt][h * 2 + 1] - mean) * inv * s_g[c + 1] + s_b[c + 1];
                    float p0 = __shfl_xor_sync(0xffffffffu, a0, 1);
                    float p1 = __shfl_xor_sync(0xffffffffu, a1, 1);
                    if ((t4 & 1) == 0) {
                        float4 rs = *(const float4*)(er + c);
                        float4 o;
                        o.x = rs.x + a0; o.y = rs.y + a1;
                        o.z = rs.z + p0; o.w = rs.w + p1;
                        *(float4*)(orow + c) = o;
                        red_v4(srow + c, a0, a1, p0, p1);
                    }
                }
                if (wcol == 0 && t4 == 0) atomicAdd(g_counts + t, 1.f);
            }
        }
        barg(gid);   // protect XA/XB/s_sum before next tile
    }
}

// ======================= NODE kernel (SIMT, small) =======================
#define TILE_M  128
#define KC      32
#define SST     132

__global__ void __launch_bounds__(256)
node_kernel(const float* __restrict__ tgt_feat,
            const float* __restrict__ W1,       // We2t
            const float* __restrict__ W2,       // Wt2t
            const float* __restrict__ gamma,
            const float* __restrict__ beta,
            float*       __restrict__ out,
            int M)
{
    __shared__ float xs[KC][SST];
    __shared__ float ws[KC][SST];
    __shared__ float s_inv[TILE_M];

    const int tid = threadIdx.x;
    const int tx  = tid & 15;
    const int ty  = tid >> 4;
    const int m0  = blockIdx.x * TILE_M;

    for (int i = tid; i < TILE_M; i += 256) {
        int row = m0 + i;
        s_inv[i] = (row < M) ? 1.f / fmaxf(g_counts[row], 1.f) : 0.f;
    }
    __syncthreads();

    float acc[8][8];
#pragma unroll
    for (int r = 0; r < 8; r++)
#pragma unroll
        for (int c = 0; c < 8; c++) acc[r][c] = 0.f;

#pragma unroll 1
    for (int pass = 0; pass < 2; pass++) {
        const float* __restrict__ W = pass ? W2 : W1;
#pragma unroll 1
        for (int kc = 0; kc < D / KC; kc++) {
            const int k0 = kc * KC;
            for (int i = tid; i < D * KC; i += 256) {
                int n = i >> 5, kl = i & 31;
                ws[kl][n] = W[n * D + k0 + kl];
            }
            for (int i = tid; i < TILE_M * KC; i += 256) {
                int m = i >> 5, kl = i & 31;
                float v = 0.f;
                long gm = (long)(m0 + m);
                if (gm < M) {
                    if (pass == 0) v = g_sums[gm * D + k0 + kl] * s_inv[m];
                    else           v = tgt_feat[gm * D + k0 + kl];
                }
                xs[kl][m] = v;
            }
            __syncthreads();
#pragma unroll
            for (int k = 0; k < KC; k++) {
                float4 xa = *(const float4*)&xs[k][ty * 4];
                float4 xb = *(const float4*)&xs[k][64 + ty * 4];
                float4 wa = *(const float4*)&ws[k][tx * 4];
                float4 wb = *(const float4*)&ws[k][64 + tx * 4];
                float xv[8] = {xa.x, xa.y, xa.z, xa.w, xb.x, xb.y, xb.z, xb.w};
                float wv[8] = {wa.x, wa.y, wa.z, wa.w, wb.x, wb.y, wb.z, wb.w};
#pragma unroll
                for (int r = 0; r < 8; r++)
#pragma unroll
                    for (int c = 0; c < 8; c++) acc[r][c] += xv[r] * wv[c];
            }
            __syncthreads();
        }
    }

    float g[8], b[8];
#pragma unroll
    for (int c = 0; c < 8; c++) {
        int n = (c < 4) ? (tx * 4 + c) : (64 + tx * 4 + (c - 4));
        g[c] = gamma[n];
        b[c] = beta[n];
    }

#pragma unroll
    for (int r = 0; r < 8; r++) {
        const int mrow = (r < 4) ? (ty * 4 + r) : (64 + ty * 4 + (r - 4));
        const long gm  = (long)(m0 + mrow);

        float sum = 0.f, sq = 0.f;
#pragma unroll
        for (int c = 0; c < 8; c++) {
            float v  = acc[r][c];
            float sv = v / (1.f + __expf(-v));
            acc[r][c] = sv;
            sum += sv; sq += sv * sv;
        }
#pragma unroll
        for (int o = 8; o >= 1; o >>= 1) {
            sum += __shfl_xor_sync(0xffffffffu, sum, o);
            sq  += __shfl_xor_sync(0xffffffffu, sq,  o);
        }
        const float mean = sum * (1.f / 128.f);
        const float var  = sq * (1.f / 128.f) - mean * mean;
        const float inv  = rsqrtf(var + 1e-5f);

        if (gm >= M) continue;

        const float* __restrict__ resrow = tgt_feat + gm * D;
        float4 r0 = *(const float4*)&resrow[tx * 4];
        float4 r1 = *(const float4*)&resrow[64 + tx * 4];
        float a0 = (acc[r][0] - mean) * inv * g[0] + b[0];
        float a1 = (acc[r][1] - mean) * inv * g[1] + b[1];
        float a2 = (acc[r][2] - mean) * inv * g[2] + b[2];
        float a3 = (acc[r][3] - mean) * inv * g[3] + b[3];
        float a4 = (acc[r][4] - mean) * inv * g[4] + b[4];
        float a5 = (acc[r][5] - mean) * inv * g[5] + b[5];
        float a6 = (acc[r][6] - mean) * inv * g[6] + b[6];
        float a7 = (acc[r][7] - mean) * inv * g[7] + b[7];
        *(float4*)&out[gm * D + tx * 4] =
            make_float4(r0.x + a0, r0.y + a1, r0.z + a2, r0.w + a3);
        *(float4*)&out[gm * D + 64 + tx * 4] =
            make_float4(r1.x + a4, r1.y + a5, r1.z + a6, r1.w + a7);
    }
}

// ======================= launch =======================
extern "C" void kernel_launch(void* const* d_in, const int* in_sizes, int n_in,
                              void* d_out, int out_size) {
    const float* src_feat  = (const float*)d_in[0];
    const float* tgt_feat  = (const float*)d_in[1];
    const float* edge_feat = (const float*)d_in[2];
    const float* Ws2e      = (const float*)d_in[3];
    const float* We2e      = (const float*)d_in[4];
    const float* We2t      = (const float*)d_in[5];
    const float* Wt2t      = (const float*)d_in[6];
    const float* gamma1    = (const float*)d_in[7];
    const float* beta1     = (const float*)d_in[8];
    const float* gamma2    = (const float*)d_in[9];
    const float* beta2     = (const float*)d_in[10];
    const int*   src_idx   = (const int*)d_in[11];
    const int*   tgt_idx   = (const int*)d_in[12];
    float*       out       = (float*)d_out;

    cudaFuncSetAttribute(edge_kernel,
                         cudaFuncAttributeMaxDynamicSharedMemorySize, SMEM_BYTES);

    zero_scratch_kernel<<<2048, 256>>>();

    edge_kernel<<<148, 512, SMEM_BYTES>>>(
        src_feat, tgt_feat, edge_feat, Ws2e, We2e, gamma1, beta1,
        src_idx, tgt_idx, out);

    node_kernel<<<(N_TGT + TILE_M - 1) / TILE_M, 256>>>(
        tgt_feat, We2t, Wt2t, gamma2, beta2, out + (size_t)N_EDGE * D, N_TGT);
}

// round 11
// speedup vs baseline: 1.6713x; 1.0112x over previous
#include <cuda_runtime.h>
#include <cuda_fp16.h>
#include <cstdint>

#define D 128
#define N_TGT 40000
#define N_EDGE 640000
#define TILE64 64
#define NT64 (N_EDGE / TILE64)          // 10000
#define SROW 68                          // u32 per fp16 smem row (64 data + 4 pad)
#define XBLK (TILE64 * SROW)             // 4352 u32 per X buffer

// ---------------- scratch ----------------
__device__ float g_sums[(size_t)N_TGT * D];
__device__ float g_counts[N_TGT];

__global__ void zero_scratch_kernel() {
    const int n = N_TGT * D;
    const int total = n + N_TGT;
    for (int i = blockIdx.x * blockDim.x + threadIdx.x; i < total;
         i += gridDim.x * blockDim.x) {
        if (i < n) g_sums[i] = 0.f;
        else       g_counts[i - n] = 0.f;
    }
}

// ---------------- helpers ----------------
__device__ __forceinline__ uint32_t smem_addr_u32(const void* p) {
    uint32_t a;
    asm("{ .reg .u64 t; cvta.to.shared.u64 t, %1; cvt.u32.u64 %0, t; }"
        : "=r"(a) : "l"(p));
    return a;
}
__device__ __forceinline__ uint32_t ph2(float x, float y) {
    __half2 h = __floats2half2_rn(x, y);
    return *(uint32_t*)&h;
}
__device__ __forceinline__ void ldsm_x4(uint32_t& r0, uint32_t& r1,
                                        uint32_t& r2, uint32_t& r3, uint32_t a) {
    asm volatile("ldmatrix.sync.aligned.m8n8.x4.shared.b16 {%0,%1,%2,%3}, [%4];"
        : "=r"(r0), "=r"(r1), "=r"(r2), "=r"(r3) : "r"(a));
}
__device__ __forceinline__ void ldsm_x2(uint32_t& r0, uint32_t& r1, uint32_t a) {
    asm volatile("ldmatrix.sync.aligned.m8n8.x2.shared.b16 {%0,%1}, [%2];"
        : "=r"(r0), "=r"(r1) : "r"(a));
}
__device__ __forceinline__ void mma16(float* d, uint32_t a0, uint32_t a1,
                                      uint32_t a2, uint32_t a3,
                                      uint32_t b0, uint32_t b1) {
    asm volatile(
        "mma.sync.aligned.m16n8k16.row.col.f32.f16.f16.f32 "
        "{%0,%1,%2,%3},{%4,%5,%6,%7},{%8,%9},{%0,%1,%2,%3};"
        : "+f"(d[0]), "+f"(d[1]), "+f"(d[2]), "+f"(d[3])
        : "r"(a0), "r"(a1), "r"(a2), "r"(a3), "r"(b0), "r"(b1));
}
__device__ __forceinline__ void red_v4(float* p, float a, float b,
                                       float c, float d) {
    asm volatile("red.relaxed.gpu.global.add.v4.f32 [%0], {%1, %2, %3, %4};"
        :: "l"(p), "f"(a), "f"(b), "f"(c), "f"(d) : "memory");
}
__device__ __forceinline__ void barg(int gid) {
    asm volatile("bar.sync %0, 128;" :: "r"(gid + 1) : "memory");
}

// ---------------- smem layout (u32 offsets) ----------------
#define UOFF_W1  0
#define UOFF_W2  8704
#define UOFF_X   17408          // group g: XA = UOFF_X + g*2*XBLK, XB = XA + XBLK
#define UOFF_SUM 52224          // + g*128 floats
#define UOFF_SQ  52736          // + g*128 floats
#define UOFF_G   53248
#define UOFF_B   53376
#define SMEM_U32 53504
#define SMEM_BYTES (SMEM_U32 * 4)   // 214016

// ======================= EDGE kernel (4 groups x 128 threads) ==============
__global__ void __launch_bounds__(512, 1)
edge_kernel(const float* __restrict__ src_feat,
            const float* __restrict__ tgt_feat,
            const float* __restrict__ edge_feat,
            const float* __restrict__ W1,
            const float* __restrict__ W2,
            const float* __restrict__ gamma,
            const float* __restrict__ beta,
            const int*   __restrict__ src_idx,
            const int*   __restrict__ tgt_idx,
            float*       __restrict__ out)
{
    extern __shared__ uint32_t smu[];
    const uint32_t smb = smem_addr_u32(smu);

    const int tid  = threadIdx.x;
    const int gid  = tid >> 7;          // group 0-3
    const int lt   = tid & 127;         // local tid within group
    const int wid  = lt >> 5;           // local warp 0-3
    const int lane = tid & 31;
    const int g    = lane >> 2;
    const int t4   = lane & 3;
    const int wr   = wid & 1;           // row band (32 rows)
    const int wcol = wid >> 1;          // column half 0/1

    float* s_sum = (float*)(smu + UOFF_SUM + gid * 128);
    float* s_sq  = (float*)(smu + UOFF_SQ  + gid * 128);
    float* s_g   = (float*)(smu + UOFF_G);
    float* s_b   = (float*)(smu + UOFF_B);
    const uint32_t xa_off = UOFF_X + gid * 2 * XBLK;
    const uint32_t xb_off = xa_off + XBLK;

    // ldmatrix lane geometry
    const int a_r  = (lane & 7) + ((lane >> 3) & 1) * 8;
    const int a_cu = ((lane >> 4) & 1) * 4;
    const int lb   = lane & 15;
    const int b_r  = lb & 7;
    const int b_cu = ((lb >> 3) & 1) * 4;

    if (tid < 128) { s_g[tid] = gamma[tid]; s_b[tid] = beta[tid]; }

    // stage both weight tiles once (fp16), all 512 threads
    for (int i = tid; i < 128 * 32; i += 512) {
        int n = i >> 5, k4 = (i & 31) << 2;
        float4 a = *(const float4*)(W1 + n * D + k4);
        float4 b = *(const float4*)(W2 + n * D + k4);
        uint2 ua, ub;
        ua.x = ph2(a.x, a.y); ua.y = ph2(a.z, a.w);
        ub.x = ph2(b.x, b.y); ub.y = ph2(b.z, b.w);
        *(uint2*)(smu + UOFF_W1 + n * SROW + (k4 >> 1)) = ua;
        *(uint2*)(smu + UOFF_W2 + n * SROW + (k4 >> 1)) = ub;
    }
    __syncthreads();

    for (int tile = blockIdx.x * 4 + gid; tile < NT64; tile += gridDim.x * 4) {
        const int m0 = tile * TILE64;

        // ---- stage X0 = src[si]+tgt[ti], X1 = edge (fp16); 64 rows ----
#pragma unroll
        for (int j = 0; j < 16; j++) {
            int i = lt + 128 * j;
            int row = i >> 5, k4 = (i & 31) << 2;
            int si = src_idx[m0 + row];
            int ti = tgt_idx[m0 + row];
            float4 a = *(const float4*)(src_feat + (size_t)si * D + k4);
            float4 b = *(const float4*)(tgt_feat + (size_t)ti * D + k4);
            float4 e = *(const float4*)(edge_feat + (size_t)(m0 + row) * D + k4);
            uint2 u0, u1;
            u0.x = ph2(a.x + b.x, a.y + b.y);
            u0.y = ph2(a.z + b.z, a.w + b.w);
            u1.x = ph2(e.x, e.y);
            u1.y = ph2(e.z, e.w);
            *(uint2*)(smu + xa_off + row * SROW + (k4 >> 1)) = u0;
            *(uint2*)(smu + xb_off + row * SROW + (k4 >> 1)) = u1;
        }
        barg(gid);

        float acc[2][8][4];
#pragma unroll
        for (int mt = 0; mt < 2; mt++)
#pragma unroll
            for (int nt = 0; nt < 8; nt++)
#pragma unroll
                for (int j = 0; j < 4; j++) acc[mt][nt][j] = 0.f;

        // ---- pass 1: acc += XA @ W1^T ----
#pragma unroll
        for (int ks = 0; ks < 8; ks++) {
            uint32_t a0[2], a1[2], a2[2], a3[2];
#pragma unroll
            for (int mt = 0; mt < 2; mt++) {
                uint32_t ad = smb + (xa_off + (wr * 32 + mt * 16 + a_r) * SROW
                                     + ks * 8 + a_cu) * 4;
                ldsm_x4(a0[mt], a1[mt], a2[mt], a3[mt], ad);
            }
#pragma unroll
            for (int nt = 0; nt < 8; nt++) {
                uint32_t bd = smb + (UOFF_W1 + (wcol * 64 + nt * 8 + b_r) * SROW
                                     + ks * 8 + b_cu) * 4;
                uint32_t b0, b1;
                ldsm_x2(b0, b1, bd);
                mma16(acc[0][nt], a0[0], a1[0], a2[0], a3[0], b0, b1);
                mma16(acc[1][nt], a0[1], a1[1], a2[1], a3[1], b0, b1);
            }
        }
        // ---- pass 2: acc += XB @ W2^T (disjoint buffers, no sync) ----
#pragma unroll
        for (int ks = 0; ks < 8; ks++) {
            uint32_t a0[2], a1[2], a2[2], a3[2];
#pragma unroll
            for (int mt = 0; mt < 2; mt++) {
                uint32_t ad = smb + (xb_off + (wr * 32 + mt * 16 + a_r) * SROW
                                     + ks * 8 + a_cu) * 4;
                ldsm_x4(a0[mt], a1[mt], a2[mt], a3[mt], ad);
            }
#pragma unroll
            for (int nt = 0; nt < 8; nt++) {
                uint32_t bd = smb + (UOFF_W2 + (wcol * 64 + nt * 8 + b_r) * SROW
                                     + ks * 8 + b_cu) * 4;
                uint32_t b0, b1;
                ldsm_x2(b0, b1, bd);
                mma16(acc[0][nt], a0[0], a1[0], a2[0], a3[0], b0, b1);
                mma16(acc[1][nt], a0[1], a1[1], a2[1], a3[1], b0, b1);
            }
        }

        // ---- silu + LN partials ----
#pragma unroll
        for (int mt = 0; mt < 2; mt++) {
#pragma unroll
            for (int h = 0; h < 2; h++) {
                float s = 0.f, q = 0.f;
#pragma unroll
                for (int nt = 0; nt < 8; nt++) {
#pragma unroll
                    for (int j = 0; j < 2; j++) {
                        float v  = acc[mt][nt][h * 2 + j];
                        float sv = v / (1.f + __expf(-v));
                        acc[mt][nt][h * 2 + j] = sv;
                        s += sv; q += sv * sv;
                    }
                }
                s += __shfl_xor_sync(0xffffffffu, s, 1);
                s += __shfl_xor_sync(0xffffffffu, s, 2);
                q += __shfl_xor_sync(0xffffffffu, q, 1);
                q += __shfl_xor_sync(0xffffffffu, q, 2);
                if (t4 == 0) {
                    int row = wr * 32 + mt * 16 + h * 8 + g;
                    s_sum[wcol * 64 + row] = s;
                    s_sq[wcol * 64 + row]  = q;
                }
            }
        }
        barg(gid);

        // ---- LN + residual + out + scatter ----
#pragma unroll
        for (int mt = 0; mt < 2; mt++) {
#pragma unroll
            for (int h = 0; h < 2; h++) {
                const int row = wr * 32 + mt * 16 + h * 8 + g;
                const float tsum = s_sum[row] + s_sum[64 + row];
                const float tsq  = s_sq[row]  + s_sq[64 + row];
                const float mean = tsum * (1.f / 128.f);
                const float inv  = rsqrtf(tsq * (1.f / 128.f) - mean * mean + 1e-5f);
                const int    t   = tgt_idx[m0 + row];
                const size_t gm  = (size_t)(m0 + row);
                float* __restrict__ srow = g_sums + (size_t)t * D;
                const float* __restrict__ er = edge_feat + gm * D;
                float* __restrict__ orow = out + gm * D;
#pragma unroll
                for (int nt = 0; nt < 8; nt++) {
                    const int c = wcol * 64 + nt * 8 + t4 * 2;
                    float a0 = (acc[mt][nt][h * 2 + 0] - mean) * inv * s_g[c + 0] + s_b[c + 0];
                    float a1 = (acc[mt][nt][h * 2 + 1] - mean) * inv * s_g[c + 1] + s_b[c + 1];
                    float p0 = __shfl_xor_sync(0xffffffffu, a0, 1);
                    float p1 = __shfl_xor_sync(0xffffffffu, a1, 1);
                    if ((t4 & 1) == 0) {
                        float4 rs = *(const float4*)(er + c);
                        float4 o;
                        o.x = rs.x + a0; o.y = rs.y + a1;
                        o.z = rs.z + p0; o.w = rs.w + p1;
                        *(float4*)(orow + c) = o;
                        red_v4(srow + c, a0, a1, p0, p1);
                    }
                }
                if (wcol == 0 && t4 == 0) atomicAdd(g_counts + t, 1.f);
            }
        }
        barg(gid);   // protect XA/XB/s_sum before next tile
    }
}

// ======================= NODE kernel (SIMT, small) =======================
#define TILE_M  128
#define KC      32
#define SST     132

__global__ void __launch_bounds__(256)
node_kernel(const float* __restrict__ tgt_feat,
            const float* __restrict__ W1,       // We2t
            const float* __restrict__ W2,       // Wt2t
            const float* __restrict__ gamma,
            const float* __restrict__ beta,
            float*       __restrict__ out,
            int M)
{
    __shared__ float xs[KC][SST];
    __shared__ float ws[KC][SST];
    __shared__ float s_inv[TILE_M];

    const int tid = threadIdx.x;
    const int tx  = tid & 15;
    const int ty  = tid >> 4;
    const int m0  = blockIdx.x * TILE_M;

    for (int i = tid; i < TILE_M; i += 256) {
        int row = m0 + i;
        s_inv[i] = (row < M) ? 1.f / fmaxf(g_counts[row], 1.f) : 0.f;
    }
    __syncthreads();

    float acc[8][8];
#pragma unroll
    for (int r = 0; r < 8; r++)
#pragma unroll
        for (int c = 0; c < 8; c++) acc[r][c] = 0.f;

#pragma unroll 1
    for (int pass = 0; pass < 2; pass++) {
        const float* __restrict__ W = pass ? W2 : W1;
#pragma unroll 1
        for (int kc = 0; kc < D / KC; kc++) {
            const int k0 = kc * KC;
            for (int i = tid; i < D * KC; i += 256) {
                int n = i >> 5, kl = i & 31;
                ws[kl][n] = W[n * D + k0 + kl];
            }
            for (int i = tid; i < TILE_M * KC; i += 256) {
                int m = i >> 5, kl = i & 31;
                float v = 0.f;
                long gm = (long)(m0 + m);
                if (gm < M) {
                    if (pass == 0) v = g_sums[gm * D + k0 + kl] * s_inv[m];
                    else           v = tgt_feat[gm * D + k0 + kl];
                }
                xs[kl][m] = v;
            }
            __syncthreads();
#pragma unroll
            for (int k = 0; k < KC; k++) {
                float4 xa = *(const float4*)&xs[k][ty * 4];
                float4 xb = *(const float4*)&xs[k][64 + ty * 4];
                float4 wa = *(const float4*)&ws[k][tx * 4];
                float4 wb = *(const float4*)&ws[k][64 + tx * 4];
                float xv[8] = {xa.x, xa.y, xa.z, xa.w, xb.x, xb.y, xb.z, xb.w};
                float wv[8] = {wa.x, wa.y, wa.z, wa.w, wb.x, wb.y, wb.z, wb.w};
#pragma unroll
                for (int r = 0; r < 8; r++)
#pragma unroll
                    for (int c = 0; c < 8; c++) acc[r][c] += xv[r] * wv[c];
            }
            __syncthreads();
        }
    }

    float g[8], b[8];
#pragma unroll
    for (int c = 0; c < 8; c++) {
        int n = (c < 4) ? (tx * 4 + c) : (64 + tx * 4 + (c - 4));
        g[c] = gamma[n];
        b[c] = beta[n];
    }

#pragma unroll
    for (int r = 0; r < 8; r++) {
        const int mrow = (r < 4) ? (ty * 4 + r) : (64 + ty * 4 + (r - 4));
        const long gm  = (long)(m0 + mrow);

        float sum = 0.f, sq = 0.f;
#pragma unroll
        for (int c = 0; c < 8; c++) {
            float v  = acc[r][c];
            float sv = v / (1.f + __expf(-v));
            acc[r][c] = sv;
            sum += sv; sq += sv * sv;
        }
#pragma unroll
        for (int o = 8; o >= 1; o >>= 1) {
            sum += __shfl_xor_sync(0xffffffffu, sum, o);
            sq  += __shfl_xor_sync(0xffffffffu, sq,  o);
        }
        const float mean = sum * (1.f / 128.f);
        const float var  = sq * (1.f / 128.f) - mean * mean;
        const float inv  = rsqrtf(var + 1e-5f);

        if (gm >= M) continue;

        const float* __restrict__ resrow = tgt_feat + gm * D;
        float4 r0 = *(const float4*)&resrow[tx * 4];
        float4 r1 = *(const float4*)&resrow[64 + tx * 4];
        float a0 = (acc[r][0] - mean) * inv * g[0] + b[0];
        float a1 = (acc[r][1] - mean) * inv * g[1] + b[1];
        float a2 = (acc[r][2] - mean) * inv * g[2] + b[2];
        float a3 = (acc[r][3] - mean) * inv * g[3] + b[3];
        float a4 = (acc[r][4] - mean) * inv * g[4] + b[4];
        float a5 = (acc[r][5] - mean) * inv * g[5] + b[5];
        float a6 = (acc[r][6] - mean) * inv * g[6] + b[6];
        float a7 = (acc[r][7] - mean) * inv * g[7] + b[7];
        *(float4*)&out[gm * D + tx * 4] =
            make_float4(r0.x + a0, r0.y + a1, r0.z + a2, r0.w + a3);
        *(float4*)&out[gm * D + 64 + tx * 4] =
            make_float4(r1.x + a4, r1.y + a5, r1.z + a6, r1.w + a7);
    }
}

// ======================= launch =======================
extern "C" void kernel_launch(void* const* d_in, const int* in_sizes, int n_in,
                              void* d_out, int out_size) {
    const float* src_feat  = (const float*)d_in[0];
    const float* tgt_feat  = (const float*)d_in[1];
    const float* edge_feat = (const float*)d_in[2];
    const float* Ws2e      = (const float*)d_in[3];
    const float* We2e      = (const float*)d_in[4];
    const float* We2t      = (const float*)d_in[5];
    const float* Wt2t      = (const float*)d_in[6];
    const float* gamma1    = (const float*)d_in[7];
    const float* beta1     = (const float*)d_in[8];
    const float* gamma2    = (const float*)d_in[9];
    const float* beta2     = (const float*)d_in[10];
    const int*   src_idx   = (const int*)d_in[11];
    const int*   tgt_idx   = (const int*)d_in[12];
    float*       out       = (float*)d_out;

    cudaFuncSetAttribute(edge_kernel,
                         cudaFuncAttributeMaxDynamicSharedMemorySize, SMEM_BYTES);

    zero_scratch_kernel<<<2048, 256>>>();

    edge_kernel<<<148, 512, SMEM_BYTES>>>(
        src_feat, tgt_feat, edge_feat, Ws2e, We2e, gamma1, beta1,
        src_idx, tgt_idx, out);

    node_kernel<<<(N_TGT + TILE_M - 1) / TILE_M, 256>>>(
        tgt_feat, We2t, Wt2t, gamma2, beta2, out + (size_t)N_EDGE * D, N_TGT);
}

// round 12
// speedup vs baseline: 1.9465x; 1.1647x over previous
#include <cuda_runtime.h>
#include <cuda_fp16.h>
#include <cstdint>

#define D 128
#define N_TGT 40000
#define N_EDGE 640000
#define TILE64 64
#define NT64 (N_EDGE / TILE64)          // 10000
#define NTN64 (N_TGT / TILE64)          // 625
#define SROW 68                          // u32 per fp16 smem row (64 data + 4 pad)
#define XBLK (TILE64 * SROW)             // 4352 u32 per X buffer

// ---------------- scratch ----------------
__device__ float g_sums[(size_t)N_TGT * D];
__device__ float g_counts[N_TGT];

__global__ void zero_scratch_kernel() {
    const int n = N_TGT * D;
    const int total = n + N_TGT;
    for (int i = blockIdx.x * blockDim.x + threadIdx.x; i < total;
         i += gridDim.x * blockDim.x) {
        if (i < n) g_sums[i] = 0.f;
        else       g_counts[i - n] = 0.f;
    }
}

// ---------------- helpers ----------------
__device__ __forceinline__ uint32_t smem_addr_u32(const void* p) {
    uint32_t a;
    asm("{ .reg .u64 t; cvta.to.shared.u64 t, %1; cvt.u32.u64 %0, t; }"
        : "=r"(a) : "l"(p));
    return a;
}
__device__ __forceinline__ uint32_t ph2(float x, float y) {
    __half2 h = __floats2half2_rn(x, y);
    return *(uint32_t*)&h;
}
__device__ __forceinline__ void ldsm_x4(uint32_t& r0, uint32_t& r1,
                                        uint32_t& r2, uint32_t& r3, uint32_t a) {
    asm volatile("ldmatrix.sync.aligned.m8n8.x4.shared.b16 {%0,%1,%2,%3}, [%4];"
        : "=r"(r0), "=r"(r1), "=r"(r2), "=r"(r3) : "r"(a));
}
__device__ __forceinline__ void ldsm_x2(uint32_t& r0, uint32_t& r1, uint32_t a) {
    asm volatile("ldmatrix.sync.aligned.m8n8.x2.shared.b16 {%0,%1}, [%2];"
        : "=r"(r0), "=r"(r1) : "r"(a));
}
__device__ __forceinline__ void mma16(float* d, uint32_t a0, uint32_t a1,
                                      uint32_t a2, uint32_t a3,
                                      uint32_t b0, uint32_t b1) {
    asm volatile(
        "mma.sync.aligned.m16n8k16.row.col.f32.f16.f16.f32 "
        "{%0,%1,%2,%3},{%4,%5,%6,%7},{%8,%9},{%0,%1,%2,%3};"
        : "+f"(d[0]), "+f"(d[1]), "+f"(d[2]), "+f"(d[3])
        : "r"(a0), "r"(a1), "r"(a2), "r"(a3), "r"(b0), "r"(b1));
}
__device__ __forceinline__ void red_v4(float* p, float a, float b,
                                       float c, float d) {
    asm volatile("red.relaxed.gpu.global.add.v4.f32 [%0], {%1, %2, %3, %4};"
        :: "l"(p), "f"(a), "f"(b), "f"(c), "f"(d) : "memory");
}
__device__ __forceinline__ void barg(int gid) {
    asm volatile("bar.sync %0, 128;" :: "r"(gid + 1) : "memory");
}

// ---------------- smem layout (u32 offsets) ----------------
#define UOFF_W1  0
#define UOFF_W2  8704
#define UOFF_X   17408          // group g: XA = UOFF_X + g*2*XBLK, XB = XA + XBLK
#define UOFF_SUM 52224          // + g*128 floats
#define UOFF_SQ  52736          // + g*128 floats
#define UOFF_G   53248
#define UOFF_B   53376
#define SMEM_U32 53504
#define SMEM_BYTES (SMEM_U32 * 4)   // 214016

// ======================= fused GEMM+LN core (edge/node) ====================
// EDGE: X0 = src[si]+tgt[ti], X1 = edge_feat, residual = edge_feat, scatter.
// NODE: X0 = g_sums*inv,      X1 = tgt_feat,  residual = tgt_feat, no scatter.
template <bool EDGE>
__global__ void __launch_bounds__(512, 1)
fused_kernel(const float* __restrict__ featA,   // EDGE: src_feat, NODE: unused
             const float* __restrict__ featB,   // EDGE: tgt_feat, NODE: tgt_feat
             const float* __restrict__ featX,   // EDGE: edge_feat, NODE: tgt_feat
             const float* __restrict__ W1,
             const float* __restrict__ W2,
             const float* __restrict__ gamma,
             const float* __restrict__ beta,
             const int*   __restrict__ src_idx,
             const int*   __restrict__ tgt_idx,
             float*       __restrict__ out)
{
    extern __shared__ uint32_t smu[];
    const uint32_t smb = smem_addr_u32(smu);

    const int tid  = threadIdx.x;
    const int gid  = tid >> 7;          // group 0-3
    const int lt   = tid & 127;         // local tid within group
    const int wid  = lt >> 5;           // local warp 0-3
    const int lane = tid & 31;
    const int g    = lane >> 2;
    const int t4   = lane & 3;
    const int wr   = wid & 1;           // row band (32 rows)
    const int wcol = wid >> 1;          // column half 0/1

    float* s_sum = (float*)(smu + UOFF_SUM + gid * 128);
    float* s_sq  = (float*)(smu + UOFF_SQ  + gid * 128);
    float* s_g   = (float*)(smu + UOFF_G);
    float* s_b   = (float*)(smu + UOFF_B);
    const uint32_t xa_off = UOFF_X + gid * 2 * XBLK;
    const uint32_t xb_off = xa_off + XBLK;

    // ldmatrix lane geometry
    const int a_r  = (lane & 7) + ((lane >> 3) & 1) * 8;
    const int a_cu = ((lane >> 4) & 1) * 4;
    const int lb   = lane & 15;
    const int b_r  = lb & 7;
    const int b_cu = ((lb >> 3) & 1) * 4;

    if (tid < 128) { s_g[tid] = gamma[tid]; s_b[tid] = beta[tid]; }

    // stage both weight tiles once (fp16), all 512 threads
    for (int i = tid; i < 128 * 32; i += 512) {
        int n = i >> 5, k4 = (i & 31) << 2;
        float4 a = *(const float4*)(W1 + n * D + k4);
        float4 b = *(const float4*)(W2 + n * D + k4);
        uint2 ua, ub;
        ua.x = ph2(a.x, a.y); ua.y = ph2(a.z, a.w);
        ub.x = ph2(b.x, b.y); ub.y = ph2(b.z, b.w);
        *(uint2*)(smu + UOFF_W1 + n * SROW + (k4 >> 1)) = ua;
        *(uint2*)(smu + UOFF_W2 + n * SROW + (k4 >> 1)) = ub;
    }
    __syncthreads();

    const int ntiles = EDGE ? NT64 : NTN64;
    for (int tile = blockIdx.x * 4 + gid; tile < ntiles; tile += gridDim.x * 4) {
        const int m0 = tile * TILE64;

        // ---- stage X0, X1 (fp16); 64 rows ----
#pragma unroll
        for (int j = 0; j < 16; j++) {
            int i = lt + 128 * j;
            int row = i >> 5, k4 = (i & 31) << 2;
            uint2 u0, u1;
            if (EDGE) {
                int si = src_idx[m0 + row];
                int ti = tgt_idx[m0 + row];
                float4 a = *(const float4*)(featA + (size_t)si * D + k4);
                float4 b = *(const float4*)(featB + (size_t)ti * D + k4);
                float4 e = *(const float4*)(featX + (size_t)(m0 + row) * D + k4);
                u0.x = ph2(a.x + b.x, a.y + b.y);
                u0.y = ph2(a.z + b.z, a.w + b.w);
                u1.x = ph2(e.x, e.y);
                u1.y = ph2(e.z, e.w);
            } else {
                size_t gm = (size_t)(m0 + row);
                float inv = 1.f / fmaxf(g_counts[gm], 1.f);
                float4 a = *(const float4*)(g_sums + gm * D + k4);
                float4 e = *(const float4*)(featX + gm * D + k4);
                u0.x = ph2(a.x * inv, a.y * inv);
                u0.y = ph2(a.z * inv, a.w * inv);
                u1.x = ph2(e.x, e.y);
                u1.y = ph2(e.z, e.w);
            }
            *(uint2*)(smu + xa_off + row * SROW + (k4 >> 1)) = u0;
            *(uint2*)(smu + xb_off + row * SROW + (k4 >> 1)) = u1;
        }
        barg(gid);

        float acc[2][8][4];
#pragma unroll
        for (int mt = 0; mt < 2; mt++)
#pragma unroll
            for (int nt = 0; nt < 8; nt++)
#pragma unroll
                for (int j = 0; j < 4; j++) acc[mt][nt][j] = 0.f;

        // ---- pass 1: acc += XA @ W1^T ----
#pragma unroll
        for (int ks = 0; ks < 8; ks++) {
            uint32_t a0[2], a1[2], a2[2], a3[2];
#pragma unroll
            for (int mt = 0; mt < 2; mt++) {
                uint32_t ad = smb + (xa_off + (wr * 32 + mt * 16 + a_r) * SROW
                                     + ks * 8 + a_cu) * 4;
                ldsm_x4(a0[mt], a1[mt], a2[mt], a3[mt], ad);
            }
#pragma unroll
            for (int nt = 0; nt < 8; nt++) {
                uint32_t bd = smb + (UOFF_W1 + (wcol * 64 + nt * 8 + b_r) * SROW
                                     + ks * 8 + b_cu) * 4;
                uint32_t b0, b1;
                ldsm_x2(b0, b1, bd);
                mma16(acc[0][nt], a0[0], a1[0], a2[0], a3[0], b0, b1);
                mma16(acc[1][nt], a0[1], a1[1], a2[1], a3[1], b0, b1);
            }
        }
        // ---- pass 2: acc += XB @ W2^T (disjoint buffers, no sync) ----
#pragma unroll
        for (int ks = 0; ks < 8; ks++) {
            uint32_t a0[2], a1[2], a2[2], a3[2];
#pragma unroll
            for (int mt = 0; mt < 2; mt++) {
                uint32_t ad = smb + (xb_off + (wr * 32 + mt * 16 + a_r) * SROW
                                     + ks * 8 + a_cu) * 4;
                ldsm_x4(a0[mt], a1[mt], a2[mt], a3[mt], ad);
            }
#pragma unroll
            for (int nt = 0; nt < 8; nt++) {
                uint32_t bd = smb + (UOFF_W2 + (wcol * 64 + nt * 8 + b_r) * SROW
                                     + ks * 8 + b_cu) * 4;
                uint32_t b0, b1;
                ldsm_x2(b0, b1, bd);
                mma16(acc[0][nt], a0[0], a1[0], a2[0], a3[0], b0, b1);
                mma16(acc[1][nt], a0[1], a1[1], a2[1], a3[1], b0, b1);
            }
        }

        // ---- silu + LN partials ----
#pragma unroll
        for (int mt = 0; mt < 2; mt++) {
#pragma unroll
            for (int h = 0; h < 2; h++) {
                float s = 0.f, q = 0.f;
#pragma unroll
                for (int nt = 0; nt < 8; nt++) {
#pragma unroll
                    for (int j = 0; j < 2; j++) {
                        float v  = acc[mt][nt][h * 2 + j];
                        float sv = v / (1.f + __expf(-v));
                        acc[mt][nt][h * 2 + j] = sv;
                        s += sv; q += sv * sv;
                    }
                }
                s += __shfl_xor_sync(0xffffffffu, s, 1);
                s += __shfl_xor_sync(0xffffffffu, s, 2);
                q += __shfl_xor_sync(0xffffffffu, q, 1);
                q += __shfl_xor_sync(0xffffffffu, q, 2);
                if (t4 == 0) {
                    int row = wr * 32 + mt * 16 + h * 8 + g;
                    s_sum[wcol * 64 + row] = s;
                    s_sq[wcol * 64 + row]  = q;
                }
            }
        }
        barg(gid);

        // ---- LN + residual + out (+ scatter for EDGE) ----
#pragma unroll
        for (int mt = 0; mt < 2; mt++) {
#pragma unroll
            for (int h = 0; h < 2; h++) {
                const int row = wr * 32 + mt * 16 + h * 8 + g;
                const float tsum = s_sum[row] + s_sum[64 + row];
                const float tsq  = s_sq[row]  + s_sq[64 + row];
                const float mean = tsum * (1.f / 128.f);
                const float inv  = rsqrtf(tsq * (1.f / 128.f) - mean * mean + 1e-5f);
                const size_t gm  = (size_t)(m0 + row);
                const float* __restrict__ er = featX + gm * D;
                float* __restrict__ orow = out + gm * D;
                float* __restrict__ srow = nullptr;
                int t = 0;
                if (EDGE) {
                    t = tgt_idx[m0 + row];
                    srow = g_sums + (size_t)t * D;
                }
#pragma unroll
                for (int nt = 0; nt < 8; nt++) {
                    const int c = wcol * 64 + nt * 8 + t4 * 2;
                    float a0 = (acc[mt][nt][h * 2 + 0] - mean) * inv * s_g[c + 0] + s_b[c + 0];
                    float a1 = (acc[mt][nt][h * 2 + 1] - mean) * inv * s_g[c + 1] + s_b[c + 1];
                    float p0 = __shfl_xor_sync(0xffffffffu, a0, 1);
                    float p1 = __shfl_xor_sync(0xffffffffu, a1, 1);
                    if ((t4 & 1) == 0) {
                        float4 rs = *(const float4*)(er + c);
                        float4 o;
                        o.x = rs.x + a0; o.y = rs.y + a1;
                        o.z = rs.z + p0; o.w = rs.w + p1;
                        *(float4*)(orow + c) = o;
                        if (EDGE) red_v4(srow + c, a0, a1, p0, p1);
                    }
                }
                if (EDGE && wcol == 0 && t4 == 0) atomicAdd(g_counts + t, 1.f);
            }
        }
        // no trailing barrier: XA/XB are dead after pass 2 (all warps passed
        // the LN barrier), and s_sum reuse is ordered by the next stage barrier.
    }
}

// ======================= launch =======================
extern "C" void kernel_launch(void* const* d_in, const int* in_sizes, int n_in,
                              void* d_out, int out_size) {
    const float* src_feat  = (const float*)d_in[0];
    const float* tgt_feat  = (const float*)d_in[1];
    const float* edge_feat = (const float*)d_in[2];
    const float* Ws2e      = (const float*)d_in[3];
    const float* We2e      = (const float*)d_in[4];
    const float* We2t      = (const float*)d_in[5];
    const float* Wt2t      = (const float*)d_in[6];
    const float* gamma1    = (const float*)d_in[7];
    const float* beta1     = (const float*)d_in[8];
    const float* gamma2    = (const float*)d_in[9];
    const float* beta2     = (const float*)d_in[10];
    const int*   src_idx   = (const int*)d_in[11];
    const int*   tgt_idx   = (const int*)d_in[12];
    float*       out       = (float*)d_out;

    cudaFuncSetAttribute(fused_kernel<true>,
                         cudaFuncAttributeMaxDynamicSharedMemorySize, SMEM_BYTES);
    cudaFuncSetAttribute(fused_kernel<false>,
                         cudaFuncAttributeMaxDynamicSharedMemorySize, SMEM_BYTES);

    zero_scratch_kernel<<<2048, 256>>>();

    fused_kernel<true><<<148, 512, SMEM_BYTES>>>(
        src_feat, tgt_feat, edge_feat, Ws2e, We2e, gamma1, beta1,
        src_idx, tgt_idx, out);

    fused_kernel<false><<<148, 512, SMEM_BYTES>>>(
        nullptr, tgt_feat, tgt_feat, We2t, Wt2t, gamma2, beta2,
        nullptr, nullptr, out + (size_t)N_EDGE * D);
}